// round 1
// baseline (speedup 1.0000x reference)
#include <cuda_runtime.h>
#include <math.h>

#define NTOK   16384
#define DIMV   768
#define HEADSN 12
#define DHV    64
#define DFFV   2048
#define DEPTHN 8

// ---------------- scratch (device globals: allocation-guard safe) ----------------
__device__ float g_x [NTOK*DIMV];
__device__ float g_tn[NTOK*DIMV];
__device__ float g_q [NTOK*DIMV];
__device__ float g_k [NTOK*DIMV];
__device__ float g_v [NTOK*DIMV];
__device__ float g_rv[NTOK*DIMV];
__device__ float g_o [NTOK*DIMV];
__device__ float g_h [NTOK*2*DFFV];
__device__ float g_hg[NTOK*DFFV];
__device__ float g_mix [NTOK*HEADSN];
__device__ float g_gate[NTOK*HEADSN];

// ---------------- copy ----------------
__global__ void copy_kernel(const float* __restrict__ src, float* __restrict__ dst, int n)
{
    int i = blockIdx.x * blockDim.x + threadIdx.x;
    if (i < n) dst[i] = src[i];
}

// ---------------- rmsnorm: one block per row ----------------
__global__ void rmsnorm_kernel(const float* __restrict__ in, const float* __restrict__ w,
                               float* __restrict__ out)
{
    __shared__ float red[8];
    __shared__ float snorm;
    const int row = blockIdx.x;
    const float* xr = in + (size_t)row * DIMV;
    float ss = 0.f;
    for (int c = threadIdx.x; c < DIMV; c += 256) { float vv = xr[c]; ss += vv * vv; }
    #pragma unroll
    for (int o = 16; o; o >>= 1) ss += __shfl_down_sync(0xffffffffu, ss, o);
    if ((threadIdx.x & 31) == 0) red[threadIdx.x >> 5] = ss;
    __syncthreads();
    if (threadIdx.x == 0) {
        float t = 0.f;
        #pragma unroll
        for (int i = 0; i < 8; i++) t += red[i];
        snorm = rsqrtf(t / (float)DIMV + 1e-6f);
    }
    __syncthreads();
    const float sc = snorm;
    float* orow = out + (size_t)row * DIMV;
    for (int c = threadIdx.x; c < DIMV; c += 256) orow[c] = xr[c] * sc * w[c];
}

// ---------------- SGEMM: C[M,N] = A[M,K]@B[K,N] (+bias[N]) (+res[M,N]) ----------------
// M%128==0, N%128==0, K%8==0. 256 threads, 128x128 tile, 8x8 per thread.
__global__ void __launch_bounds__(256) sgemm_kernel(
    const float* __restrict__ A, const float* __restrict__ B,
    float* __restrict__ C, const float* __restrict__ bias,
    const float* __restrict__ res, int M, int N, int K)
{
    __shared__ float As[8][128];
    __shared__ float Bs[8][128];
    const int tid = threadIdx.x;
    const int bx = blockIdx.x, by = blockIdx.y;
    const int tx = tid & 15, ty = tid >> 4;

    float acc[8][8];
    #pragma unroll
    for (int i = 0; i < 8; i++)
        #pragma unroll
        for (int j = 0; j < 8; j++) acc[i][j] = 0.f;

    const int arow = tid >> 1, acol = (tid & 1) * 4;
    const int brow = tid >> 5, bcol = (tid & 31) * 4;
    const float* Aptr = A + (size_t)(by * 128 + arow) * K + acol;
    const float* Bptr = B + (size_t)brow * N + bx * 128 + bcol;

    for (int k0 = 0; k0 < K; k0 += 8) {
        float4 a4 = *(const float4*)(Aptr + k0);
        float4 b4 = *(const float4*)(Bptr + (size_t)k0 * N);
        As[acol + 0][arow] = a4.x; As[acol + 1][arow] = a4.y;
        As[acol + 2][arow] = a4.z; As[acol + 3][arow] = a4.w;
        *(float4*)&Bs[brow][bcol] = b4;
        __syncthreads();
        #pragma unroll
        for (int kk = 0; kk < 8; kk++) {
            float ar[8], br[8];
            float4 a0 = *(const float4*)&As[kk][ty * 8];
            float4 a1 = *(const float4*)&As[kk][ty * 8 + 4];
            float4 b0 = *(const float4*)&Bs[kk][tx * 8];
            float4 b1 = *(const float4*)&Bs[kk][tx * 8 + 4];
            ar[0]=a0.x; ar[1]=a0.y; ar[2]=a0.z; ar[3]=a0.w;
            ar[4]=a1.x; ar[5]=a1.y; ar[6]=a1.z; ar[7]=a1.w;
            br[0]=b0.x; br[1]=b0.y; br[2]=b0.z; br[3]=b0.w;
            br[4]=b1.x; br[5]=b1.y; br[6]=b1.z; br[7]=b1.w;
            #pragma unroll
            for (int i = 0; i < 8; i++)
                #pragma unroll
                for (int j = 0; j < 8; j++) acc[i][j] += ar[i] * br[j];
        }
        __syncthreads();
    }

    const int cbase = bx * 128 + tx * 8;
    #pragma unroll
    for (int i = 0; i < 8; i++) {
        const int r = by * 128 + ty * 8 + i;
        float vals[8];
        #pragma unroll
        for (int j = 0; j < 8; j++) {
            float vv = acc[i][j];
            if (bias) vv += bias[cbase + j];
            if (res)  vv += res[(size_t)r * N + cbase + j];
            vals[j] = vv;
        }
        *(float4*)(C + (size_t)r * N + cbase)     = make_float4(vals[0], vals[1], vals[2], vals[3]);
        *(float4*)(C + (size_t)r * N + cbase + 4) = make_float4(vals[4], vals[5], vals[6], vals[7]);
    }
}

// ---------------- mix + gate projections: one block per token, 24 warps ----------------
__global__ void mixgate_kernel(const float* __restrict__ tn,
    const float* __restrict__ Wmix, const float* __restrict__ bmix,
    const float* __restrict__ Wg,
    float* __restrict__ mix, float* __restrict__ gate)
{
    __shared__ float row[DIMV];
    const int tok = blockIdx.x;
    for (int c = threadIdx.x; c < DIMV; c += 768) row[c] = tn[(size_t)tok * DIMV + c];
    __syncthreads();
    const int w = threadIdx.x >> 5, lane = threadIdx.x & 31;
    const float* W = (w < HEADSN) ? Wmix : Wg;
    const int col = (w < HEADSN) ? w : (w - HEADSN);
    float s = 0.f;
    for (int c = lane; c < DIMV; c += 32) s += row[c] * W[(size_t)c * HEADSN + col];
    #pragma unroll
    for (int o = 16; o; o >>= 1) s += __shfl_down_sync(0xffffffffu, s, o);
    if (lane == 0) {
        if (w < HEADSN) {
            s += bmix[col];
            mix[tok * HEADSN + col] = 1.f / (1.f + expf(-s));
        } else {
            gate[tok * HEADSN + col] = 1.f / (1.f + expf(-s));
        }
    }
}

// ---------------- v value-residual lerp + k MultiHeadRMSNorm ----------------
__global__ void vkfix_kernel(float* __restrict__ v, const float* __restrict__ rv,
    const float* __restrict__ mix, float* __restrict__ k, const float* __restrict__ kgam)
{
    __shared__ float red[24];
    const int tok = blockIdx.x;
    const int tid = threadIdx.x;           // 0..767 = h*64+d
    const int h = tid >> 6;
    const size_t idx = (size_t)tok * DIMV + tid;
    const float m = mix[tok * HEADSN + h];
    const float vv = v[idx];
    v[idx] = vv + m * (rv[idx] - vv);
    const float kk = k[idx];
    float ss = kk * kk;
    #pragma unroll
    for (int o = 16; o; o >>= 1) ss += __shfl_down_sync(0xffffffffu, ss, o);
    if ((tid & 31) == 0) red[tid >> 5] = ss;
    __syncthreads();
    float n = sqrtf(red[2 * h] + red[2 * h + 1]);
    n = fmaxf(n, 1e-12f);
    k[idx] = (kk / n) * (kgam[tid] + 1.f) * 8.0f;   // sqrt(DH)=8
}

// ---------------- spatial attention: seq=256 non-causal, no rotary ----------------
// grid (HEADS, B*T=64), 256 threads, 192KB dynamic smem
__global__ void __launch_bounds__(256) attn_spatial_kernel(
    const float* __restrict__ q, const float* __restrict__ k, const float* __restrict__ v,
    const float* __restrict__ gate, float* __restrict__ o)
{
    extern __shared__ float sm[];
    float* Ks = sm;                 // 256*64
    float* Vs = sm + 256 * 64;
    float* Qs = sm + 2 * 256 * 64;
    const int h  = blockIdx.x;
    const size_t tok0 = (size_t)blockIdx.y * 256;
    const int tid = threadIdx.x;

    #pragma unroll
    for (int it = 0; it < 16; it++) {
        const int idx = tid + it * 256;      // float4 index 0..4095
        const int row = idx >> 4;
        const int d4  = idx & 15;
        const size_t g4 = ((tok0 + row) * DIMV + h * DHV) / 4 + d4;
        ((float4*)Ks)[row * 16 + d4] = ((const float4*)k)[g4];
        ((float4*)Vs)[row * 16 + d4] = ((const float4*)v)[g4];
        ((float4*)Qs)[row * 16 + d4] = ((const float4*)q)[g4];
    }
    __syncthreads();

    float qr[64];
    #pragma unroll
    for (int d = 0; d < 64; d++) qr[d] = Qs[tid * 64 + d];

    float sc[256];
    float mx = -1e30f;
    for (int j = 0; j < 256; j++) {
        float a = 0.f;
        #pragma unroll
        for (int d = 0; d < 64; d++) a += qr[d] * Ks[j * 64 + d];
        a *= 0.125f;                          // DH^-0.5
        a = tanhf(a * 0.02f) * 50.f;          // softclamp
        sc[j] = a;
        mx = fmaxf(mx, a);
    }
    float sum = 0.f;
    for (int j = 0; j < 256; j++) { float e = expf(sc[j] - mx); sc[j] = e; sum += e; }
    const float inv = 1.f / sum;

    float oc[64];
    #pragma unroll
    for (int d = 0; d < 64; d++) oc[d] = 0.f;
    for (int j = 0; j < 256; j++) {
        const float p = sc[j] * inv;
        #pragma unroll
        for (int d = 0; d < 64; d++) oc[d] += p * Vs[j * 64 + d];
    }
    const float g = gate[(tok0 + tid) * HEADSN + h];
    float* ob = o + (tok0 + tid) * DIMV + h * DHV;
    #pragma unroll
    for (int d = 0; d < 64; d++) ob[d] = oc[d] * g;
}

// ---------------- time attention: seq=32 causal + rotary ----------------
// grid (HEADS, B*S=512), 32 threads (1 warp)
__global__ void attn_time_kernel(
    const float* __restrict__ q, const float* __restrict__ k, const float* __restrict__ v,
    const float* __restrict__ gate, float* __restrict__ o)
{
    __shared__ float Ks[32 * 64];
    __shared__ float Vs[32 * 64];
    const int h  = blockIdx.x;
    const int bs = blockIdx.y;           // 0..511
    const int b = bs >> 8, s = bs & 255;
    const int lane = threadIdx.x;        // = time position t of this thread's row
    const size_t tok = ((size_t)(b * 32 + lane) * 256 + s);
    const size_t base = tok * DIMV + h * DHV;

    // rotary angles for position t=lane
    float cr[32], sr[32];
    #pragma unroll
    for (int d = 0; d < 32; d++) {
        float fr = (float)lane * powf(10000.f, -(float)d / 32.f);
        cr[d] = cosf(fr); sr[d] = sinf(fr);
    }

    // load K row (apply rotary), V row
    {
        float kr[64];
        #pragma unroll
        for (int d = 0; d < 64; d++) { kr[d] = k[base + d]; Vs[lane * 64 + d] = v[base + d]; }
        #pragma unroll
        for (int d = 0; d < 32; d++) {
            Ks[lane * 64 + d]      = kr[d]      * cr[d] - kr[d + 32] * sr[d];
            Ks[lane * 64 + d + 32] = kr[d + 32] * cr[d] + kr[d]      * sr[d];
        }
    }
    __syncwarp();

    // q row with rotary
    float qr[64];
    {
        float qt[64];
        #pragma unroll
        for (int d = 0; d < 64; d++) qt[d] = q[base + d];
        #pragma unroll
        for (int d = 0; d < 32; d++) {
            qr[d]      = qt[d]      * cr[d] - qt[d + 32] * sr[d];
            qr[d + 32] = qt[d + 32] * cr[d] + qt[d]      * sr[d];
        }
    }

    float sc[32];
    float mx = -1e30f;
    #pragma unroll
    for (int j = 0; j < 32; j++) {
        float a;
        if (j <= lane) {
            a = 0.f;
            #pragma unroll
            for (int d = 0; d < 64; d++) a += qr[d] * Ks[j * 64 + d];
            a *= 0.125f;
            a = tanhf(a * 0.02f) * 50.f;
        } else {
            a = -1e30f;
        }
        sc[j] = a;
        mx = fmaxf(mx, a);
    }
    float sum = 0.f;
    #pragma unroll
    for (int j = 0; j < 32; j++) { float e = expf(sc[j] - mx); sc[j] = e; sum += e; }
    const float inv = 1.f / sum;

    float oc[64];
    #pragma unroll
    for (int d = 0; d < 64; d++) oc[d] = 0.f;
    #pragma unroll
    for (int j = 0; j < 32; j++) {
        const float p = sc[j] * inv;
        #pragma unroll
        for (int d = 0; d < 64; d++) oc[d] += p * Vs[j * 64 + d];
    }
    const float g = gate[tok * HEADSN + h];
    #pragma unroll
    for (int d = 0; d < 64; d++) o[base + d] = oc[d] * g;
}

// ---------------- geglu: out = a * gelu_exact(g) ----------------
__global__ void geglu_kernel(const float* __restrict__ hin, float* __restrict__ out)
{
    const int idx = blockIdx.x * blockDim.x + threadIdx.x;
    if (idx >= NTOK * DFFV) return;
    const int row = idx / DFFV, c = idx % DFFV;
    const float a = hin[(size_t)row * 2 * DFFV + c];
    const float g = hin[(size_t)row * 2 * DFFV + DFFV + c];
    const float ge = 0.5f * g * (1.f + erff(g * 0.70710678118654752f));
    out[idx] = a * ge;
}

// ---------------- host orchestration ----------------
extern "C" void kernel_launch(void* const* d_in, const int* in_sizes, int n_in,
                              void* d_out, int out_size)
{
    const float* tokens       = (const float*)d_in[0];
    const float* attn_norm_w  = (const float*)d_in[1];
    const float* Wq           = (const float*)d_in[2];
    const float* Wk           = (const float*)d_in[3];
    const float* Wv           = (const float*)d_in[4];
    const float* Wo           = (const float*)d_in[5];
    const float* Wg           = (const float*)d_in[6];
    const float* Wmix         = (const float*)d_in[7];
    const float* bmix         = (const float*)d_in[8];
    const float* kgam         = (const float*)d_in[9];
    const float* ff_norm_w    = (const float*)d_in[10];
    const float* Win          = (const float*)d_in[11];
    const float* b_in         = (const float*)d_in[12];
    const float* Wout         = (const float*)d_in[13];
    const float* b_out        = (const float*)d_in[14];
    const float* vr_norm_w    = (const float*)d_in[15];
    const float* vr_W         = (const float*)d_in[16];
    const float* final_norm_w = (const float*)d_in[17];

    float *x, *tn, *q, *k, *v, *rv, *o, *hbuf, *hg, *mix, *gate;
    cudaGetSymbolAddress((void**)&x,    g_x);
    cudaGetSymbolAddress((void**)&tn,   g_tn);
    cudaGetSymbolAddress((void**)&q,    g_q);
    cudaGetSymbolAddress((void**)&k,    g_k);
    cudaGetSymbolAddress((void**)&v,    g_v);
    cudaGetSymbolAddress((void**)&rv,   g_rv);
    cudaGetSymbolAddress((void**)&o,    g_o);
    cudaGetSymbolAddress((void**)&hbuf, g_h);
    cudaGetSymbolAddress((void**)&hg,   g_hg);
    cudaGetSymbolAddress((void**)&mix,  g_mix);
    cudaGetSymbolAddress((void**)&gate, g_gate);

    const int SPATIAL_SMEM = 3 * 256 * 64 * 4;   // 192 KB
    cudaFuncSetAttribute(attn_spatial_kernel,
                         cudaFuncAttributeMaxDynamicSharedMemorySize, SPATIAL_SMEM);

    const dim3 grid768(DIMV / 128, NTOK / 128);         // (6,128)
    const dim3 grid4096((2 * DFFV) / 128, NTOK / 128);  // (32,128)

    // value residual from original tokens
    rmsnorm_kernel<<<NTOK, 256>>>(tokens, vr_norm_w, tn);
    sgemm_kernel<<<grid768, 256>>>(tn, vr_W, rv, nullptr, nullptr, NTOK, DIMV, DIMV);
    copy_kernel<<<(NTOK * DIMV + 255) / 256, 256>>>(tokens, x, NTOK * DIMV);

    for (int i = 0; i < DEPTHN; i++) {
        const float* wq_i   = Wq   + (size_t)i * DIMV * DIMV;
        const float* wk_i   = Wk   + (size_t)i * DIMV * DIMV;
        const float* wv_i   = Wv   + (size_t)i * DIMV * DIMV;
        const float* wo_i   = Wo   + (size_t)i * DIMV * DIMV;
        const float* wg_i   = Wg   + (size_t)i * DIMV * HEADSN;
        const float* wmix_i = Wmix + (size_t)i * DIMV * HEADSN;
        const float* bmix_i = bmix + (size_t)i * HEADSN;
        const float* kgam_i = kgam + (size_t)i * HEADSN * DHV;
        const float* win_i  = Win  + (size_t)i * DIMV * 2 * DFFV;
        const float* bin_i  = b_in + (size_t)i * 2 * DFFV;
        const float* wout_i = Wout + (size_t)i * DFFV * DIMV;
        const float* bout_i = b_out + (size_t)i * DIMV;

        // attention sublayer
        rmsnorm_kernel<<<NTOK, 256>>>(x, attn_norm_w + (size_t)i * DIMV, tn);
        sgemm_kernel<<<grid768, 256>>>(tn, wq_i, q, nullptr, nullptr, NTOK, DIMV, DIMV);
        sgemm_kernel<<<grid768, 256>>>(tn, wk_i, k, nullptr, nullptr, NTOK, DIMV, DIMV);
        sgemm_kernel<<<grid768, 256>>>(tn, wv_i, v, nullptr, nullptr, NTOK, DIMV, DIMV);
        mixgate_kernel<<<NTOK, 768>>>(tn, wmix_i, bmix_i, wg_i, mix, gate);
        vkfix_kernel<<<NTOK, 768>>>(v, rv, mix, k, kgam_i);

        if ((i + 1) % 4 == 0)
            attn_time_kernel<<<dim3(HEADSN, 512), 32>>>(q, k, v, gate, o);
        else
            attn_spatial_kernel<<<dim3(HEADSN, 64), 256, SPATIAL_SMEM>>>(q, k, v, gate, o);

        sgemm_kernel<<<grid768, 256>>>(o, wo_i, x, nullptr, x, NTOK, DIMV, DIMV);

        // feedforward sublayer
        rmsnorm_kernel<<<NTOK, 256>>>(x, ff_norm_w + (size_t)i * DIMV, tn);
        sgemm_kernel<<<grid4096, 256>>>(tn, win_i, hbuf, bin_i, nullptr, NTOK, 2 * DFFV, DIMV);
        geglu_kernel<<<(NTOK * DFFV + 255) / 256, 256>>>(hbuf, hg);
        sgemm_kernel<<<grid768, 256>>>(hg, wout_i, x, bout_i, x, NTOK, DIMV, DFFV);
    }

    rmsnorm_kernel<<<NTOK, 256>>>(x, final_norm_w, (float*)d_out);
}

// round 3
// speedup vs baseline: 2.4931x; 2.4931x over previous
#include <cuda_runtime.h>
#include <cstdint>
#include <math.h>

#define NTOK   16384
#define DIMV   768
#define HEADSN 12
#define DHV    64
#define DFFV   2048
#define DEPTHN 8

// ---------------- scratch (device globals: allocation-guard safe) ----------------
__device__ float g_x [NTOK*DIMV];
__device__ float g_tn[NTOK*DIMV];
__device__ float g_q [NTOK*DIMV];
__device__ float g_k [NTOK*DIMV];
__device__ float g_v [NTOK*DIMV];
__device__ float g_rv[NTOK*DIMV];
__device__ float g_o [NTOK*DIMV];
__device__ float g_h [NTOK*2*DFFV];
__device__ float g_hg[NTOK*DFFV];
__device__ float g_mix [NTOK*HEADSN];
__device__ float g_gate[NTOK*HEADSN];

// ---------------- copy ----------------
__global__ void copy_kernel(const float* __restrict__ src, float* __restrict__ dst, int n)
{
    int i = blockIdx.x * blockDim.x + threadIdx.x;
    if (i < n) dst[i] = src[i];
}

// ---------------- rmsnorm: one block per row ----------------
__global__ void rmsnorm_kernel(const float* __restrict__ in, const float* __restrict__ w,
                               float* __restrict__ out)
{
    __shared__ float red[8];
    __shared__ float snorm;
    const int row = blockIdx.x;
    const float* xr = in + (size_t)row * DIMV;
    float ss = 0.f;
    for (int c = threadIdx.x; c < DIMV; c += 256) { float vv = xr[c]; ss += vv * vv; }
    #pragma unroll
    for (int o = 16; o; o >>= 1) ss += __shfl_down_sync(0xffffffffu, ss, o);
    if ((threadIdx.x & 31) == 0) red[threadIdx.x >> 5] = ss;
    __syncthreads();
    if (threadIdx.x == 0) {
        float t = 0.f;
        #pragma unroll
        for (int i = 0; i < 8; i++) t += red[i];
        snorm = rsqrtf(t / (float)DIMV + 1e-6f);
    }
    __syncthreads();
    const float sc = snorm;
    float* orow = out + (size_t)row * DIMV;
    for (int c = threadIdx.x; c < DIMV; c += 256) orow[c] = xr[c] * sc * w[c];
}

// ---------------- tf32 tensor-core GEMM ----------------
// C[M,N] = A[M,K]@B[K,N] (+bias[N]) (+res[M,N]); M%128==0, N%128==0, K%32==0
// 128x128x32 block tile, 256 threads = 8 warps, each warp 64x32 via m16n8k8 tf32 mma.
// As[128][36] row-major (pad 4), Bs[32][132] (pad 4): all fragment LDS conflict-free.
// cp.async double-buffered.

__device__ __forceinline__ void cp16(uint32_t s, const void* g) {
    asm volatile("cp.async.ca.shared.global [%0], [%1], 16;" :: "r"(s), "l"(g));
}
__device__ __forceinline__ uint32_t f2tf(float x) {
    uint32_t r; asm("cvt.rna.tf32.f32 %0, %1;" : "=r"(r) : "f"(x)); return r;
}

#define SMEM_TILE_FLOATS (128*36 + 32*132)   // 8832 floats per buffer
#define GEMM_SMEM_BYTES  (2 * SMEM_TILE_FLOATS * 4)  // 70656 B

__global__ void __launch_bounds__(256, 2) gemm_tf32_kernel(
    const float* __restrict__ A, const float* __restrict__ B,
    float* __restrict__ C, const float* __restrict__ bias,
    const float* __restrict__ res, int M, int N, int K)
{
    extern __shared__ float sm[];
    const int tid = threadIdx.x;
    const int bx = blockIdx.x, by = blockIdx.y;
    const int warp = tid >> 5, lane = tid & 31;
    const int wrow = warp >> 2, wcol = warp & 3;   // 2 x 4 warp grid
    const int grp = lane >> 2, qid = lane & 3;

    float acc[4][4][4];
    #pragma unroll
    for (int a = 0; a < 4; a++)
        #pragma unroll
        for (int b = 0; b < 4; b++)
            #pragma unroll
            for (int c = 0; c < 4; c++) acc[a][b][c] = 0.f;

    const int KT = K >> 5;

    // ---- async tile loader ----
    auto loadTile = [&](int kt, int buf) {
        float* As = sm + buf * SMEM_TILE_FLOATS;
        float* Bs = As + 128 * 36;
        uint32_t sA = (uint32_t)__cvta_generic_to_shared(As);
        uint32_t sB = (uint32_t)__cvta_generic_to_shared(Bs);
        const int k0 = kt * 32;
        #pragma unroll
        for (int i = 0; i < 4; i++) {
            int idx = tid + i * 256;            // 1024 float4 of A
            int r = idx >> 3, c4 = (idx & 7) << 2;
            cp16(sA + (uint32_t)(r * 36 + c4) * 4,
                 A + (size_t)(by * 128 + r) * K + k0 + c4);
        }
        #pragma unroll
        for (int i = 0; i < 4; i++) {
            int idx = tid + i * 256;            // 1024 float4 of B
            int r = idx >> 5, c4 = (idx & 31) << 2;
            cp16(sB + (uint32_t)(r * 132 + c4) * 4,
                 B + (size_t)(k0 + r) * N + bx * 128 + c4);
        }
        asm volatile("cp.async.commit_group;");
    };

    auto computeTile = [&](int buf) {
        const float* As = sm + buf * SMEM_TILE_FLOATS;
        const float* Bs = As + 128 * 36;
        #pragma unroll
        for (int kk = 0; kk < 4; kk++) {
            const int kb = kk * 8 + qid;
            uint32_t af[4][4], bf[4][2];
            #pragma unroll
            for (int mt = 0; mt < 4; mt++) {
                const int m = wrow * 64 + mt * 16 + grp;
                af[mt][0] = f2tf(As[m * 36 + kb]);
                af[mt][1] = f2tf(As[(m + 8) * 36 + kb]);
                af[mt][2] = f2tf(As[m * 36 + kb + 4]);
                af[mt][3] = f2tf(As[(m + 8) * 36 + kb + 4]);
            }
            #pragma unroll
            for (int nt = 0; nt < 4; nt++) {
                const int n = wcol * 32 + nt * 8 + grp;
                bf[nt][0] = f2tf(Bs[kb * 132 + n]);
                bf[nt][1] = f2tf(Bs[(kb + 4) * 132 + n]);
            }
            #pragma unroll
            for (int mt = 0; mt < 4; mt++)
                #pragma unroll
                for (int nt = 0; nt < 4; nt++)
                    asm volatile(
                        "mma.sync.aligned.m16n8k8.row.col.f32.tf32.tf32.f32 "
                        "{%0,%1,%2,%3}, {%4,%5,%6,%7}, {%8,%9}, {%0,%1,%2,%3};"
                        : "+f"(acc[mt][nt][0]), "+f"(acc[mt][nt][1]),
                          "+f"(acc[mt][nt][2]), "+f"(acc[mt][nt][3])
                        : "r"(af[mt][0]), "r"(af[mt][1]), "r"(af[mt][2]), "r"(af[mt][3]),
                          "r"(bf[nt][0]), "r"(bf[nt][1]));
        }
    };

    // ---- pipelined mainloop ----
    loadTile(0, 0);
    for (int kt = 0; kt < KT; kt++) {
        const int cur = kt & 1;
        if (kt + 1 < KT) {
            loadTile(kt + 1, 1 - cur);
            asm volatile("cp.async.wait_group 1;");
        } else {
            asm volatile("cp.async.wait_group 0;");
        }
        __syncthreads();
        computeTile(cur);
        __syncthreads();
    }

    // ---- epilogue ----
    #pragma unroll
    for (int mt = 0; mt < 4; mt++) {
        #pragma unroll
        for (int nt = 0; nt < 4; nt++) {
            const int r0 = by * 128 + wrow * 64 + mt * 16 + grp;
            const int c0 = bx * 128 + wcol * 32 + nt * 8 + qid * 2;
            float v0 = acc[mt][nt][0], v1 = acc[mt][nt][1];
            float v2 = acc[mt][nt][2], v3 = acc[mt][nt][3];
            if (bias) {
                const float b0 = bias[c0], b1 = bias[c0 + 1];
                v0 += b0; v1 += b1; v2 += b0; v3 += b1;
            }
            if (res) {
                const float2 ra = *(const float2*)(res + (size_t)r0 * N + c0);
                const float2 rb = *(const float2*)(res + (size_t)(r0 + 8) * N + c0);
                v0 += ra.x; v1 += ra.y; v2 += rb.x; v3 += rb.y;
            }
            *(float2*)(C + (size_t)r0 * N + c0)       = make_float2(v0, v1);
            *(float2*)(C + (size_t)(r0 + 8) * N + c0) = make_float2(v2, v3);
        }
    }
}

// ---------------- mix + gate projections: one block per token, 24 warps ----------------
__global__ void mixgate_kernel(const float* __restrict__ tn,
    const float* __restrict__ Wmix, const float* __restrict__ bmix,
    const float* __restrict__ Wg,
    float* __restrict__ mix, float* __restrict__ gate)
{
    __shared__ float row[DIMV];
    const int tok = blockIdx.x;
    for (int c = threadIdx.x; c < DIMV; c += 768) row[c] = tn[(size_t)tok * DIMV + c];
    __syncthreads();
    const int w = threadIdx.x >> 5, lane = threadIdx.x & 31;
    const float* W = (w < HEADSN) ? Wmix : Wg;
    const int col = (w < HEADSN) ? w : (w - HEADSN);
    float s = 0.f;
    for (int c = lane; c < DIMV; c += 32) s += row[c] * W[(size_t)c * HEADSN + col];
    #pragma unroll
    for (int o = 16; o; o >>= 1) s += __shfl_down_sync(0xffffffffu, s, o);
    if (lane == 0) {
        if (w < HEADSN) {
            s += bmix[col];
            mix[tok * HEADSN + col] = 1.f / (1.f + expf(-s));
        } else {
            gate[tok * HEADSN + col] = 1.f / (1.f + expf(-s));
        }
    }
}

// ---------------- v value-residual lerp + k MultiHeadRMSNorm ----------------
__global__ void vkfix_kernel(float* __restrict__ v, const float* __restrict__ rv,
    const float* __restrict__ mix, float* __restrict__ k, const float* __restrict__ kgam)
{
    __shared__ float red[24];
    const int tok = blockIdx.x;
    const int tid = threadIdx.x;           // 0..767 = h*64+d
    const int h = tid >> 6;
    const size_t idx = (size_t)tok * DIMV + tid;
    const float m = mix[tok * HEADSN + h];
    const float vv = v[idx];
    v[idx] = vv + m * (rv[idx] - vv);
    const float kk = k[idx];
    float ss = kk * kk;
    #pragma unroll
    for (int o = 16; o; o >>= 1) ss += __shfl_down_sync(0xffffffffu, ss, o);
    if ((tid & 31) == 0) red[tid >> 5] = ss;
    __syncthreads();
    float n = sqrtf(red[2 * h] + red[2 * h + 1]);
    n = fmaxf(n, 1e-12f);
    k[idx] = (kk / n) * (kgam[tid] + 1.f) * 8.0f;   // sqrt(DH)=8
}

// ---------------- spatial attention: seq=256 non-causal, no rotary ----------------
__global__ void __launch_bounds__(256) attn_spatial_kernel(
    const float* __restrict__ q, const float* __restrict__ k, const float* __restrict__ v,
    const float* __restrict__ gate, float* __restrict__ o)
{
    extern __shared__ float sm[];
    float* Ks = sm;                 // 256*64
    float* Vs = sm + 256 * 64;
    float* Qs = sm + 2 * 256 * 64;
    const int h  = blockIdx.x;
    const size_t tok0 = (size_t)blockIdx.y * 256;
    const int tid = threadIdx.x;

    #pragma unroll
    for (int it = 0; it < 16; it++) {
        const int idx = tid + it * 256;
        const int row = idx >> 4;
        const int d4  = idx & 15;
        const size_t g4 = ((tok0 + row) * DIMV + h * DHV) / 4 + d4;
        ((float4*)Ks)[row * 16 + d4] = ((const float4*)k)[g4];
        ((float4*)Vs)[row * 16 + d4] = ((const float4*)v)[g4];
        ((float4*)Qs)[row * 16 + d4] = ((const float4*)q)[g4];
    }
    __syncthreads();

    float qr[64];
    #pragma unroll
    for (int d = 0; d < 64; d++) qr[d] = Qs[tid * 64 + d];

    float sc[256];
    float mx = -1e30f;
    for (int j = 0; j < 256; j++) {
        float a = 0.f;
        #pragma unroll
        for (int d = 0; d < 64; d++) a += qr[d] * Ks[j * 64 + d];
        a *= 0.125f;
        a = tanhf(a * 0.02f) * 50.f;
        sc[j] = a;
        mx = fmaxf(mx, a);
    }
    float sum = 0.f;
    for (int j = 0; j < 256; j++) { float e = expf(sc[j] - mx); sc[j] = e; sum += e; }
    const float inv = 1.f / sum;

    float oc[64];
    #pragma unroll
    for (int d = 0; d < 64; d++) oc[d] = 0.f;
    for (int j = 0; j < 256; j++) {
        const float p = sc[j] * inv;
        #pragma unroll
        for (int d = 0; d < 64; d++) oc[d] += p * Vs[j * 64 + d];
    }
    const float g = gate[(tok0 + tid) * HEADSN + h];
    float* ob = o + (tok0 + tid) * DIMV + h * DHV;
    #pragma unroll
    for (int d = 0; d < 64; d++) ob[d] = oc[d] * g;
}

// ---------------- time attention: seq=32 causal + rotary ----------------
__global__ void attn_time_kernel(
    const float* __restrict__ q, const float* __restrict__ k, const float* __restrict__ v,
    const float* __restrict__ gate, float* __restrict__ o)
{
    __shared__ float Ks[32 * 64];
    __shared__ float Vs[32 * 64];
    const int h  = blockIdx.x;
    const int bs = blockIdx.y;
    const int b = bs >> 8, s = bs & 255;
    const int lane = threadIdx.x;
    const size_t tok = ((size_t)(b * 32 + lane) * 256 + s);
    const size_t base = tok * DIMV + h * DHV;

    float cr[32], sr[32];
    #pragma unroll
    for (int d = 0; d < 32; d++) {
        float fr = (float)lane * powf(10000.f, -(float)d / 32.f);
        cr[d] = cosf(fr); sr[d] = sinf(fr);
    }

    {
        float kr[64];
        #pragma unroll
        for (int d = 0; d < 64; d++) { kr[d] = k[base + d]; Vs[lane * 64 + d] = v[base + d]; }
        #pragma unroll
        for (int d = 0; d < 32; d++) {
            Ks[lane * 64 + d]      = kr[d]      * cr[d] - kr[d + 32] * sr[d];
            Ks[lane * 64 + d + 32] = kr[d + 32] * cr[d] + kr[d]      * sr[d];
        }
    }
    __syncwarp();

    float qr[64];
    {
        float qt[64];
        #pragma unroll
        for (int d = 0; d < 64; d++) qt[d] = q[base + d];
        #pragma unroll
        for (int d = 0; d < 32; d++) {
            qr[d]      = qt[d]      * cr[d] - qt[d + 32] * sr[d];
            qr[d + 32] = qt[d + 32] * cr[d] + qt[d]      * sr[d];
        }
    }

    float sc[32];
    float mx = -1e30f;
    #pragma unroll
    for (int j = 0; j < 32; j++) {
        float a;
        if (j <= lane) {
            a = 0.f;
            #pragma unroll
            for (int d = 0; d < 64; d++) a += qr[d] * Ks[j * 64 + d];
            a *= 0.125f;
            a = tanhf(a * 0.02f) * 50.f;
        } else {
            a = -1e30f;
        }
        sc[j] = a;
        mx = fmaxf(mx, a);
    }
    float sum = 0.f;
    #pragma unroll
    for (int j = 0; j < 32; j++) { float e = expf(sc[j] - mx); sc[j] = e; sum += e; }
    const float inv = 1.f / sum;

    float oc[64];
    #pragma unroll
    for (int d = 0; d < 64; d++) oc[d] = 0.f;
    #pragma unroll
    for (int j = 0; j < 32; j++) {
        const float p = sc[j] * inv;
        #pragma unroll
        for (int d = 0; d < 64; d++) oc[d] += p * Vs[j * 64 + d];
    }
    const float g = gate[tok * HEADSN + h];
    #pragma unroll
    for (int d = 0; d < 64; d++) o[base + d] = oc[d] * g;
}

// ---------------- geglu: out = a * gelu_exact(g) ----------------
__global__ void geglu_kernel(const float* __restrict__ hin, float* __restrict__ out)
{
    const int idx = blockIdx.x * blockDim.x + threadIdx.x;
    if (idx >= NTOK * DFFV) return;
    const int row = idx / DFFV, c = idx % DFFV;
    const float a = hin[(size_t)row * 2 * DFFV + c];
    const float g = hin[(size_t)row * 2 * DFFV + DFFV + c];
    const float ge = 0.5f * g * (1.f + erff(g * 0.70710678118654752f));
    out[idx] = a * ge;
}

// ---------------- host orchestration ----------------
extern "C" void kernel_launch(void* const* d_in, const int* in_sizes, int n_in,
                              void* d_out, int out_size)
{
    const float* tokens       = (const float*)d_in[0];
    const float* attn_norm_w  = (const float*)d_in[1];
    const float* Wq           = (const float*)d_in[2];
    const float* Wk           = (const float*)d_in[3];
    const float* Wv           = (const float*)d_in[4];
    const float* Wo           = (const float*)d_in[5];
    const float* Wg           = (const float*)d_in[6];
    const float* Wmix         = (const float*)d_in[7];
    const float* bmix         = (const float*)d_in[8];
    const float* kgam         = (const float*)d_in[9];
    const float* ff_norm_w    = (const float*)d_in[10];
    const float* Win          = (const float*)d_in[11];
    const float* b_in         = (const float*)d_in[12];
    const float* Wout         = (const float*)d_in[13];
    const float* b_out        = (const float*)d_in[14];
    const float* vr_norm_w    = (const float*)d_in[15];
    const float* vr_W         = (const float*)d_in[16];
    const float* final_norm_w = (const float*)d_in[17];

    float *x, *tn, *q, *k, *v, *rv, *o, *hbuf, *hg, *mix, *gate;
    cudaGetSymbolAddress((void**)&x,    g_x);
    cudaGetSymbolAddress((void**)&tn,   g_tn);
    cudaGetSymbolAddress((void**)&q,    g_q);
    cudaGetSymbolAddress((void**)&k,    g_k);
    cudaGetSymbolAddress((void**)&v,    g_v);
    cudaGetSymbolAddress((void**)&rv,   g_rv);
    cudaGetSymbolAddress((void**)&o,    g_o);
    cudaGetSymbolAddress((void**)&hbuf, g_h);
    cudaGetSymbolAddress((void**)&hg,   g_hg);
    cudaGetSymbolAddress((void**)&mix,  g_mix);
    cudaGetSymbolAddress((void**)&gate, g_gate);

    const int SPATIAL_SMEM = 3 * 256 * 64 * 4;   // 192 KB
    cudaFuncSetAttribute(attn_spatial_kernel,
                         cudaFuncAttributeMaxDynamicSharedMemorySize, SPATIAL_SMEM);
    cudaFuncSetAttribute(gemm_tf32_kernel,
                         cudaFuncAttributeMaxDynamicSharedMemorySize, GEMM_SMEM_BYTES);

    const dim3 grid768(DIMV / 128, NTOK / 128);         // (6,128)
    const dim3 grid4096((2 * DFFV) / 128, NTOK / 128);  // (32,128)

    // value residual from original tokens
    rmsnorm_kernel<<<NTOK, 256>>>(tokens, vr_norm_w, tn);
    gemm_tf32_kernel<<<grid768, 256, GEMM_SMEM_BYTES>>>(tn, vr_W, rv, nullptr, nullptr, NTOK, DIMV, DIMV);
    copy_kernel<<<(NTOK * DIMV + 255) / 256, 256>>>(tokens, x, NTOK * DIMV);

    for (int i = 0; i < DEPTHN; i++) {
        const float* wq_i   = Wq   + (size_t)i * DIMV * DIMV;
        const float* wk_i   = Wk   + (size_t)i * DIMV * DIMV;
        const float* wv_i   = Wv   + (size_t)i * DIMV * DIMV;
        const float* wo_i   = Wo   + (size_t)i * DIMV * DIMV;
        const float* wg_i   = Wg   + (size_t)i * DIMV * HEADSN;
        const float* wmix_i = Wmix + (size_t)i * DIMV * HEADSN;
        const float* bmix_i = bmix + (size_t)i * HEADSN;
        const float* kgam_i = kgam + (size_t)i * HEADSN * DHV;
        const float* win_i  = Win  + (size_t)i * DIMV * 2 * DFFV;
        const float* bin_i  = b_in + (size_t)i * 2 * DFFV;
        const float* wout_i = Wout + (size_t)i * DFFV * DIMV;
        const float* bout_i = b_out + (size_t)i * DIMV;

        // attention sublayer
        rmsnorm_kernel<<<NTOK, 256>>>(x, attn_norm_w + (size_t)i * DIMV, tn);
        gemm_tf32_kernel<<<grid768, 256, GEMM_SMEM_BYTES>>>(tn, wq_i, q, nullptr, nullptr, NTOK, DIMV, DIMV);
        gemm_tf32_kernel<<<grid768, 256, GEMM_SMEM_BYTES>>>(tn, wk_i, k, nullptr, nullptr, NTOK, DIMV, DIMV);
        gemm_tf32_kernel<<<grid768, 256, GEMM_SMEM_BYTES>>>(tn, wv_i, v, nullptr, nullptr, NTOK, DIMV, DIMV);
        mixgate_kernel<<<NTOK, 768>>>(tn, wmix_i, bmix_i, wg_i, mix, gate);
        vkfix_kernel<<<NTOK, 768>>>(v, rv, mix, k, kgam_i);

        if ((i + 1) % 4 == 0)
            attn_time_kernel<<<dim3(HEADSN, 512), 32>>>(q, k, v, gate, o);
        else
            attn_spatial_kernel<<<dim3(HEADSN, 64), 256, SPATIAL_SMEM>>>(q, k, v, gate, o);

        gemm_tf32_kernel<<<grid768, 256, GEMM_SMEM_BYTES>>>(o, wo_i, x, nullptr, x, NTOK, DIMV, DIMV);

        // feedforward sublayer
        rmsnorm_kernel<<<NTOK, 256>>>(x, ff_norm_w + (size_t)i * DIMV, tn);
        gemm_tf32_kernel<<<grid4096, 256, GEMM_SMEM_BYTES>>>(tn, win_i, hbuf, bin_i, nullptr, NTOK, 2 * DFFV, DIMV);
        geglu_kernel<<<(NTOK * DFFV + 255) / 256, 256>>>(hbuf, hg);
        gemm_tf32_kernel<<<grid768, 256, GEMM_SMEM_BYTES>>>(hg, wout_i, x, bout_i, x, NTOK, DIMV, DFFV);
    }

    rmsnorm_kernel<<<NTOK, 256>>>(x, final_norm_w, (float*)d_out);
}

// round 5
// speedup vs baseline: 2.7172x; 1.0899x over previous
#include <cuda_runtime.h>
#include <cstdint>
#include <math.h>

#define NTOK   16384
#define DIMV   768
#define HEADSN 12
#define DHV    64
#define DFFV   2048
#define DEPTHN 8

// ---------------- scratch (device globals: allocation-guard safe) ----------------
__device__ float g_x [NTOK*DIMV];
__device__ float g_tn[NTOK*DIMV];
__device__ float g_q [NTOK*DIMV];
__device__ float g_k [NTOK*DIMV];
__device__ float g_v [NTOK*DIMV];
__device__ float g_rv[NTOK*DIMV];
__device__ float g_o [NTOK*DIMV];
__device__ float g_h [NTOK*2*DFFV];
__device__ float g_hg[NTOK*DFFV];
__device__ float g_mix [NTOK*HEADSN];
__device__ float g_gate[NTOK*HEADSN];
__device__ float g_wt[7077888];     // per-layer transposed weights [N,K]

// ---------------- small helpers ----------------
__device__ __forceinline__ void cp16(uint32_t s, const void* g) {
    asm volatile("cp.async.ca.shared.global [%0], [%1], 16;" :: "r"(s), "l"(g));
}
__device__ __forceinline__ float rtf(float x) {
    uint32_t r; asm("cvt.rna.tf32.f32 %0, %1;" : "=r"(r) : "f"(x));
    return __uint_as_float(r);
}

#define MBAR_INIT(addr, count) \
    asm volatile("mbarrier.init.shared.b64 [%0], %1;" \
        :: "r"((uint32_t)(addr)), "r"((uint32_t)(count)) : "memory")

#define MBAR_WAIT(mbar_smem_addr, phase_parity) do { \
    uint32_t _mbar = (uint32_t)(mbar_smem_addr); \
    uint32_t _parity = (uint32_t)(phase_parity); \
    uint32_t _done; \
    asm volatile( \
        "{\n\t" \
        ".reg .pred p;\n\t" \
        "mbarrier.try_wait.parity.acquire.cta.shared::cta.b64 p, [%1], %2;\n\t" \
        "selp.b32 %0, 1, 0, p;\n\t" \
        "}" \
        : "=r"(_done) : "r"(_mbar), "r"(_parity) : "memory"); \
    if (!_done) { \
        asm volatile( \
            "{\n\t" \
            ".reg .pred P1;\n\t" \
            "WAIT_LOOP_%=:\n\t" \
            "mbarrier.try_wait.parity.acquire.cta.shared::cta.b64 P1, [%0], %1, 0x989680;\n\t" \
            "@P1 bra.uni WAIT_DONE_%=;\n\t" \
            "bra.uni WAIT_LOOP_%=;\n\t" \
            "WAIT_DONE_%=:\n\t" \
            "}" \
            :: "r"(_mbar), "r"(_parity) : "memory"); \
    } \
} while(0)

// ---------------- unified GEMM smem budget ----------------
#define NSTG 3
#define TCG_SMEM (1024 + NSTG * 32768)   // 99328 B (covers both paths)

// ---------------- copy ----------------
__global__ void copy_kernel(const float* __restrict__ src, float* __restrict__ dst, int n)
{
    int i = blockIdx.x * blockDim.x + threadIdx.x;
    if (i < n) dst[i] = src[i];
}

// ---------------- transpose: src[R][C] -> dst[C][R] (tf32-rounded) ----------------
__global__ void transpose_kernel(const float* __restrict__ src, float* __restrict__ dst,
                                 int R, int Ccols)
{
    __shared__ float t[32][33];
    const int c0 = blockIdx.x * 32, r0 = blockIdx.y * 32;
    const int x = threadIdx.x, y = threadIdx.y;       // 32 x 8
    #pragma unroll
    for (int i = 0; i < 32; i += 8)
        t[y + i][x] = src[(size_t)(r0 + y + i) * Ccols + c0 + x];
    __syncthreads();
    #pragma unroll
    for (int i = 0; i < 32; i += 8)
        dst[(size_t)(c0 + y + i) * R + r0 + x] = rtf(t[x][y + i]);
}

// ---------------- rmsnorm: one block per row (optional tf32 rounding) ----------------
__global__ void rmsnorm_kernel(const float* __restrict__ in, const float* __restrict__ w,
                               float* __restrict__ out, int round_out)
{
    __shared__ float red[8];
    __shared__ float snorm;
    const int row = blockIdx.x;
    const float* xr = in + (size_t)row * DIMV;
    float ss = 0.f;
    for (int c = threadIdx.x; c < DIMV; c += 256) { float vv = xr[c]; ss += vv * vv; }
    #pragma unroll
    for (int o = 16; o; o >>= 1) ss += __shfl_down_sync(0xffffffffu, ss, o);
    if ((threadIdx.x & 31) == 0) red[threadIdx.x >> 5] = ss;
    __syncthreads();
    if (threadIdx.x == 0) {
        float t = 0.f;
        #pragma unroll
        for (int i = 0; i < 8; i++) t += red[i];
        snorm = rsqrtf(t / (float)DIMV + 1e-6f);
    }
    __syncthreads();
    const float sc = snorm;
    float* orow = out + (size_t)row * DIMV;
    for (int c = threadIdx.x; c < DIMV; c += 256) {
        float vv = xr[c] * sc * w[c];
        orow[c] = round_out ? rtf(vv) : vv;
    }
}

// ============================================================================
// Unified tf32 GEMM: C[M,N] = A[M,K] @ Bt[N,K]^T (+bias[N]) (+res[M,N])
// M%128==0, N%128==0, K%32==0. 256 threads.
//   sm_103a cubin: tcgen05 kind::tf32, TMEM accumulator, 3-stage cp.async ring
//   base cubin:    mma.sync.m16n8k8 tf32 fallback (pre-rounded operands)
// ============================================================================
__global__ void __launch_bounds__(256) gemm_tc_kernel(
    const float* __restrict__ A, const float* __restrict__ Bt,
    float* __restrict__ C, const float* __restrict__ bias,
    const float* __restrict__ res, int M, int N, int K)
{
#if defined(__CUDA_ARCH_FEAT_SM103_ALL)
    // ------------------------- tcgen05 path -------------------------
    extern __shared__ char smc[];
    const uint32_t sb = (uint32_t)__cvta_generic_to_shared(smc);
    const int tid = threadIdx.x;
    const int warp = tid >> 5, lane = tid & 31;
    const int bx = blockIdx.x, by = blockIdx.y;
    const int NC = K >> 5;

    const uint32_t mbar0 = sb + 16;            // 3 ring mbarriers
    const uint32_t mbarF = sb + 16 + NSTG * 8; // final mbarrier

    if (warp == 0) {
        asm volatile("tcgen05.alloc.cta_group::1.sync.aligned.shared::cta.b32 [%0], %1;"
                     :: "r"(sb), "r"(128u) : "memory");
    }
    if (tid == 0) {
        #pragma unroll
        for (int s = 0; s < NSTG; s++) MBAR_INIT(mbar0 + s * 8, 1);
        MBAR_INIT(mbarF, 1);
    }
    __syncthreads();
    uint32_t tmem;
    asm volatile("ld.shared.b32 %0, [%1];" : "=r"(tmem) : "r"(sb));

    const uint32_t stage0 = sb + 1024;
    int ph[NSTG]; 
    #pragma unroll
    for (int s = 0; s < NSTG; s++) ph[s] = 0;

    // idesc: dtype F32(=1)@[4:5], atype/btype TF32(=2)@[7:9]/[10:12], N/8@[17:22], M/16@[24:28]
    const uint32_t IDESC = (1u << 4) | (2u << 7) | (2u << 10)
                         | ((128u / 8) << 17) | ((128u / 16) << 24);
    const uint64_t DBASE = (uint64_t(2) << 61) | (uint64_t(1) << 46)
                         | (uint64_t(64) << 32) | (uint64_t(1) << 16);

    const float* Ab = A  + (size_t)(by * 128) * K;
    const float* Bb = Bt + (size_t)(bx * 128) * K;

    for (int c = 0; c < NC; c++) {
        const int s = c % NSTG;
        const uint32_t stA = stage0 + s * 32768;
        const uint32_t stB = stA + 16384;
        if (c >= NSTG) { MBAR_WAIT(mbar0 + s * 8, ph[s]); ph[s] ^= 1; }
        const int k0 = c * 32;
        #pragma unroll
        for (int i = 0; i < 4; i++) {
            const int idx = tid + i * 256;
            const int r = idx >> 3, c16 = idx & 7;
            const uint32_t off = (uint32_t)(r * 128 + c16 * 16);
            const uint32_t sw = off ^ ((off >> 3) & 0x70);
            cp16(stA + sw, Ab + (size_t)r * K + k0 + c16 * 4);
            cp16(stB + sw, Bb + (size_t)r * K + k0 + c16 * 4);
        }
        asm volatile("cp.async.commit_group;");

        const int cm = c - (NSTG - 1);
        if (cm >= 0) {
            asm volatile("cp.async.wait_group %0;" :: "n"(NSTG - 1));
            __syncthreads();
            if (tid == 0) {
                asm volatile("fence.proxy.async.shared::cta;" ::: "memory");
                const int sm2 = cm % NSTG;
                const uint32_t mA = stage0 + sm2 * 32768;
                const uint32_t mB = mA + 16384;
                const uint64_t da = DBASE | ((uint64_t)(mA >> 4) & 0x3FFF);
                const uint64_t db = DBASE | ((uint64_t)(mB >> 4) & 0x3FFF);
                #pragma unroll
                for (int j = 0; j < 4; j++) {
                    uint32_t en = ((cm > 0) || (j > 0)) ? 1u : 0u;
                    asm volatile(
                        "{\n\t"
                        ".reg .pred p;\n\t"
                        "setp.ne.u32 p, %4, 0;\n\t"
                        "tcgen05.mma.cta_group::1.kind::tf32 [%0], %1, %2, %3, {%5,%5,%5,%5}, p;\n\t"
                        "}"
                        :: "r"(tmem), "l"(da + j * 2), "l"(db + j * 2), "r"(IDESC),
                           "r"(en), "r"(0u) : "memory");
                }
                asm volatile(
                    "tcgen05.commit.cta_group::1.mbarrier::arrive::one.shared::cluster.b64 [%0];"
                    :: "r"(mbar0 + sm2 * 8) : "memory");
            }
        }
    }

    // tail: remaining NSTG-1 chunks
    asm volatile("cp.async.wait_group 0;");
    __syncthreads();
    if (tid == 0) {
        asm volatile("fence.proxy.async.shared::cta;" ::: "memory");
        int start = NC - (NSTG - 1); if (start < 0) start = 0;
        for (int cm = start; cm < NC; cm++) {
            const int sm2 = cm % NSTG;
            const uint32_t mA = stage0 + sm2 * 32768;
            const uint32_t mB = mA + 16384;
            const uint64_t da = DBASE | ((uint64_t)(mA >> 4) & 0x3FFF);
            const uint64_t db = DBASE | ((uint64_t)(mB >> 4) & 0x3FFF);
            #pragma unroll
            for (int j = 0; j < 4; j++) {
                uint32_t en = ((cm > 0) || (j > 0)) ? 1u : 0u;
                asm volatile(
                    "{\n\t"
                    ".reg .pred p;\n\t"
                    "setp.ne.u32 p, %4, 0;\n\t"
                    "tcgen05.mma.cta_group::1.kind::tf32 [%0], %1, %2, %3, {%5,%5,%5,%5}, p;\n\t"
                    "}"
                    :: "r"(tmem), "l"(da + j * 2), "l"(db + j * 2), "r"(IDESC),
                       "r"(en), "r"(0u) : "memory");
            }
        }
        asm volatile(
            "tcgen05.commit.cta_group::1.mbarrier::arrive::one.shared::cluster.b64 [%0];"
            :: "r"(mbarF) : "memory");
    }
    MBAR_WAIT(mbarF, 0);
    asm volatile("tcgen05.fence::after_thread_sync;" ::: "memory");

    // epilogue: 8 warps; subpartition = warp&3, column half = warp>>2
    {
        const int part = warp & 3, chalf = warp >> 2;
        const int m = by * 128 + part * 32 + lane;
        float* Crow = C + (size_t)m * N;
        const float* Rrow = res ? res + (size_t)m * N : nullptr;
        #pragma unroll
        for (int nb = 0; nb < 2; nb++) {
            const int col = chalf * 64 + nb * 32;
            uint32_t d[32];
            asm volatile(
                "tcgen05.ld.sync.aligned.32x32b.x32.b32 "
                "{%0, %1, %2, %3, %4, %5, %6, %7, "
                " %8, %9, %10, %11, %12, %13, %14, %15, "
                " %16, %17, %18, %19, %20, %21, %22, %23, "
                " %24, %25, %26, %27, %28, %29, %30, %31}, [%32];"
                : "=r"(d[0]),  "=r"(d[1]),  "=r"(d[2]),  "=r"(d[3]),
                  "=r"(d[4]),  "=r"(d[5]),  "=r"(d[6]),  "=r"(d[7]),
                  "=r"(d[8]),  "=r"(d[9]),  "=r"(d[10]), "=r"(d[11]),
                  "=r"(d[12]), "=r"(d[13]), "=r"(d[14]), "=r"(d[15]),
                  "=r"(d[16]), "=r"(d[17]), "=r"(d[18]), "=r"(d[19]),
                  "=r"(d[20]), "=r"(d[21]), "=r"(d[22]), "=r"(d[23]),
                  "=r"(d[24]), "=r"(d[25]), "=r"(d[26]), "=r"(d[27]),
                  "=r"(d[28]), "=r"(d[29]), "=r"(d[30]), "=r"(d[31])
                : "r"(tmem + col));
            asm volatile("tcgen05.wait::ld.sync.aligned;" ::: "memory");
            const int c0 = bx * 128 + col;
            #pragma unroll
            for (int j = 0; j < 32; j += 4) {
                float4 vv;
                vv.x = __uint_as_float(d[j + 0]);
                vv.y = __uint_as_float(d[j + 1]);
                vv.z = __uint_as_float(d[j + 2]);
                vv.w = __uint_as_float(d[j + 3]);
                if (bias) {
                    const float4 bb = *(const float4*)(bias + c0 + j);
                    vv.x += bb.x; vv.y += bb.y; vv.z += bb.z; vv.w += bb.w;
                }
                if (Rrow) {
                    const float4 rr = *(const float4*)(Rrow + c0 + j);
                    vv.x += rr.x; vv.y += rr.y; vv.z += rr.z; vv.w += rr.w;
                }
                *(float4*)(Crow + c0 + j) = vv;
            }
        }
    }
    asm volatile("tcgen05.fence::before_thread_sync;" ::: "memory");
    __syncthreads();
    if (warp == 0) {
        asm volatile("tcgen05.dealloc.cta_group::1.sync.aligned.b32 %0, %1;"
                     :: "r"(tmem), "r"(128u));
    }
#else
    // ------------------------- mma.sync fallback -------------------------
    // Operands are pre-rounded to tf32 by producers: no per-use cvt needed.
    extern __shared__ float sm[];
    const int tid = threadIdx.x;
    const int bx = blockIdx.x, by = blockIdx.y;
    const int warp = tid >> 5, lane = tid & 31;
    const int wrow = warp >> 2, wcol = warp & 3;   // 2 x 4 warp grid
    const int grp = lane >> 2, qid = lane & 3;

    const int FB_TILE = 2 * 128 * 36;   // As + Bs floats per buffer

    float acc[4][4][4];
    #pragma unroll
    for (int a = 0; a < 4; a++)
        #pragma unroll
        for (int b = 0; b < 4; b++)
            #pragma unroll
            for (int c = 0; c < 4; c++) acc[a][b][c] = 0.f;

    const int KT = K >> 5;
    const float* Ab = A  + (size_t)(by * 128) * K;
    const float* Bb = Bt + (size_t)(bx * 128) * K;

    auto loadTile = [&](int kt, int buf) {
        float* As = sm + buf * FB_TILE;
        float* Bs = As + 128 * 36;
        uint32_t sA = (uint32_t)__cvta_generic_to_shared(As);
        uint32_t sB = (uint32_t)__cvta_generic_to_shared(Bs);
        const int k0 = kt * 32;
        #pragma unroll
        for (int i = 0; i < 4; i++) {
            int idx = tid + i * 256;
            int r = idx >> 3, c4 = (idx & 7) << 2;
            cp16(sA + (uint32_t)(r * 36 + c4) * 4, Ab + (size_t)r * K + k0 + c4);
            cp16(sB + (uint32_t)(r * 36 + c4) * 4, Bb + (size_t)r * K + k0 + c4);
        }
        asm volatile("cp.async.commit_group;");
    };

    auto computeTile = [&](int buf) {
        const float* As = sm + buf * FB_TILE;
        const float* Bs = As + 128 * 36;
        #pragma unroll
        for (int kk = 0; kk < 4; kk++) {
            const int kb = kk * 8 + qid;
            uint32_t af[4][4], bf[4][2];
            #pragma unroll
            for (int mt = 0; mt < 4; mt++) {
                const int m = wrow * 64 + mt * 16 + grp;
                af[mt][0] = *(const uint32_t*)&As[m * 36 + kb];
                af[mt][1] = *(const uint32_t*)&As[(m + 8) * 36 + kb];
                af[mt][2] = *(const uint32_t*)&As[m * 36 + kb + 4];
                af[mt][3] = *(const uint32_t*)&As[(m + 8) * 36 + kb + 4];
            }
            #pragma unroll
            for (int nt = 0; nt < 4; nt++) {
                const int n = wcol * 32 + nt * 8 + grp;
                bf[nt][0] = *(const uint32_t*)&Bs[n * 36 + kb];
                bf[nt][1] = *(const uint32_t*)&Bs[n * 36 + kb + 4];
            }
            #pragma unroll
            for (int mt = 0; mt < 4; mt++)
                #pragma unroll
                for (int nt = 0; nt < 4; nt++)
                    asm volatile(
                        "mma.sync.aligned.m16n8k8.row.col.f32.tf32.tf32.f32 "
                        "{%0,%1,%2,%3}, {%4,%5,%6,%7}, {%8,%9}, {%0,%1,%2,%3};"
                        : "+f"(acc[mt][nt][0]), "+f"(acc[mt][nt][1]),
                          "+f"(acc[mt][nt][2]), "+f"(acc[mt][nt][3])
                        : "r"(af[mt][0]), "r"(af[mt][1]), "r"(af[mt][2]), "r"(af[mt][3]),
                          "r"(bf[nt][0]), "r"(bf[nt][1]));
        }
    };

    loadTile(0, 0);
    for (int kt = 0; kt < KT; kt++) {
        const int cur = kt & 1;
        if (kt + 1 < KT) {
            loadTile(kt + 1, 1 - cur);
            asm volatile("cp.async.wait_group 1;");
        } else {
            asm volatile("cp.async.wait_group 0;");
        }
        __syncthreads();
        computeTile(cur);
        __syncthreads();
    }

    #pragma unroll
    for (int mt = 0; mt < 4; mt++) {
        #pragma unroll
        for (int nt = 0; nt < 4; nt++) {
            const int r0 = by * 128 + wrow * 64 + mt * 16 + grp;
            const int c0 = bx * 128 + wcol * 32 + nt * 8 + qid * 2;
            float v0 = acc[mt][nt][0], v1 = acc[mt][nt][1];
            float v2 = acc[mt][nt][2], v3 = acc[mt][nt][3];
            if (bias) {
                const float b0 = bias[c0], b1 = bias[c0 + 1];
                v0 += b0; v1 += b1; v2 += b0; v3 += b1;
            }
            if (res) {
                const float2 ra = *(const float2*)(res + (size_t)r0 * N + c0);
                const float2 rb = *(const float2*)(res + (size_t)(r0 + 8) * N + c0);
                v0 += ra.x; v1 += ra.y; v2 += rb.x; v3 += rb.y;
            }
            *(float2*)(C + (size_t)r0 * N + c0)       = make_float2(v0, v1);
            *(float2*)(C + (size_t)(r0 + 8) * N + c0) = make_float2(v2, v3);
        }
    }
#endif
}

// ---------------- mix + gate projections: one block per token, 24 warps ----------------
__global__ void mixgate_kernel(const float* __restrict__ tn,
    const float* __restrict__ Wmix, const float* __restrict__ bmix,
    const float* __restrict__ Wg,
    float* __restrict__ mix, float* __restrict__ gate)
{
    __shared__ float row[DIMV];
    const int tok = blockIdx.x;
    for (int c = threadIdx.x; c < DIMV; c += 768) row[c] = tn[(size_t)tok * DIMV + c];
    __syncthreads();
    const int w = threadIdx.x >> 5, lane = threadIdx.x & 31;
    const float* W = (w < HEADSN) ? Wmix : Wg;
    const int col = (w < HEADSN) ? w : (w - HEADSN);
    float s = 0.f;
    for (int c = lane; c < DIMV; c += 32) s += row[c] * W[(size_t)c * HEADSN + col];
    #pragma unroll
    for (int o = 16; o; o >>= 1) s += __shfl_down_sync(0xffffffffu, s, o);
    if (lane == 0) {
        if (w < HEADSN) {
            s += bmix[col];
            mix[tok * HEADSN + col] = 1.f / (1.f + expf(-s));
        } else {
            gate[tok * HEADSN + col] = 1.f / (1.f + expf(-s));
        }
    }
}

// ---------------- v value-residual lerp + k MultiHeadRMSNorm ----------------
__global__ void vkfix_kernel(float* __restrict__ v, const float* __restrict__ rv,
    const float* __restrict__ mix, float* __restrict__ k, const float* __restrict__ kgam)
{
    __shared__ float red[24];
    const int tok = blockIdx.x;
    const int tid = threadIdx.x;           // 0..767 = h*64+d
    const int h = tid >> 6;
    const size_t idx = (size_t)tok * DIMV + tid;
    const float m = mix[tok * HEADSN + h];
    const float vv = v[idx];
    v[idx] = vv + m * (rv[idx] - vv);
    const float kk = k[idx];
    float ss = kk * kk;
    #pragma unroll
    for (int o = 16; o; o >>= 1) ss += __shfl_down_sync(0xffffffffu, ss, o);
    if ((tid & 31) == 0) red[tid >> 5] = ss;
    __syncthreads();
    float n = sqrtf(red[2 * h] + red[2 * h + 1]);
    n = fmaxf(n, 1e-12f);
    k[idx] = (kk / n) * (kgam[tid] + 1.f) * 8.0f;   // sqrt(DH)=8
}

// ---------------- spatial attention: seq=256 non-causal, no rotary ----------------
__global__ void __launch_bounds__(256) attn_spatial_kernel(
    const float* __restrict__ q, const float* __restrict__ k, const float* __restrict__ v,
    const float* __restrict__ gate, float* __restrict__ o)
{
    extern __shared__ float sm[];
    float* Ks = sm;                 // 256*64
    float* Vs = sm + 256 * 64;
    float* Qs = sm + 2 * 256 * 64;
    const int h  = blockIdx.x;
    const size_t tok0 = (size_t)blockIdx.y * 256;
    const int tid = threadIdx.x;

    #pragma unroll
    for (int it = 0; it < 16; it++) {
        const int idx = tid + it * 256;
        const int row = idx >> 4;
        const int d4  = idx & 15;
        const size_t g4 = ((tok0 + row) * DIMV + h * DHV) / 4 + d4;
        ((float4*)Ks)[row * 16 + d4] = ((const float4*)k)[g4];
        ((float4*)Vs)[row * 16 + d4] = ((const float4*)v)[g4];
        ((float4*)Qs)[row * 16 + d4] = ((const float4*)q)[g4];
    }
    __syncthreads();

    float qr[64];
    #pragma unroll
    for (int d = 0; d < 64; d++) qr[d] = Qs[tid * 64 + d];

    float sc[256];
    float mx = -1e30f;
    for (int j = 0; j < 256; j++) {
        float a = 0.f;
        #pragma unroll
        for (int d = 0; d < 64; d++) a += qr[d] * Ks[j * 64 + d];
        a *= 0.125f;
        a = tanhf(a * 0.02f) * 50.f;
        sc[j] = a;
        mx = fmaxf(mx, a);
    }
    float sum = 0.f;
    for (int j = 0; j < 256; j++) { float e = expf(sc[j] - mx); sc[j] = e; sum += e; }
    const float inv = 1.f / sum;

    float oc[64];
    #pragma unroll
    for (int d = 0; d < 64; d++) oc[d] = 0.f;
    for (int j = 0; j < 256; j++) {
        const float p = sc[j] * inv;
        #pragma unroll
        for (int d = 0; d < 64; d++) oc[d] += p * Vs[j * 64 + d];
    }
    const float g = gate[(tok0 + tid) * HEADSN + h];
    float* ob = o + (tok0 + tid) * DIMV + h * DHV;
    #pragma unroll
    for (int d = 0; d < 64; d++) ob[d] = rtf(oc[d] * g);
}

// ---------------- time attention: seq=32 causal + rotary ----------------
__global__ void attn_time_kernel(
    const float* __restrict__ q, const float* __restrict__ k, const float* __restrict__ v,
    const float* __restrict__ gate, float* __restrict__ o)
{
    __shared__ float Ks[32 * 64];
    __shared__ float Vs[32 * 64];
    const int h  = blockIdx.x;
    const int bs = blockIdx.y;
    const int b = bs >> 8, s = bs & 255;
    const int lane = threadIdx.x;
    const size_t tok = ((size_t)(b * 32 + lane) * 256 + s);
    const size_t base = tok * DIMV + h * DHV;

    float cr[32], sr[32];
    #pragma unroll
    for (int d = 0; d < 32; d++) {
        float fr = (float)lane * powf(10000.f, -(float)d / 32.f);
        cr[d] = cosf(fr); sr[d] = sinf(fr);
    }

    {
        float kr[64];
        #pragma unroll
        for (int d = 0; d < 64; d++) { kr[d] = k[base + d]; Vs[lane * 64 + d] = v[base + d]; }
        #pragma unroll
        for (int d = 0; d < 32; d++) {
            Ks[lane * 64 + d]      = kr[d]      * cr[d] - kr[d + 32] * sr[d];
            Ks[lane * 64 + d + 32] = kr[d + 32] * cr[d] + kr[d]      * sr[d];
        }
    }
    __syncwarp();

    float qr[64];
    {
        float qt[64];
        #pragma unroll
        for (int d = 0; d < 64; d++) qt[d] = q[base + d];
        #pragma unroll
        for (int d = 0; d < 32; d++) {
            qr[d]      = qt[d]      * cr[d] - qt[d + 32] * sr[d];
            qr[d + 32] = qt[d + 32] * cr[d] + qt[d]      * sr[d];
        }
    }

    float sc[32];
    float mx = -1e30f;
    #pragma unroll
    for (int j = 0; j < 32; j++) {
        float a;
        if (j <= lane) {
            a = 0.f;
            #pragma unroll
            for (int d = 0; d < 64; d++) a += qr[d] * Ks[j * 64 + d];
            a *= 0.125f;
            a = tanhf(a * 0.02f) * 50.f;
        } else {
            a = -1e30f;
        }
        sc[j] = a;
        mx = fmaxf(mx, a);
    }
    float sum = 0.f;
    #pragma unroll
    for (int j = 0; j < 32; j++) { float e = expf(sc[j] - mx); sc[j] = e; sum += e; }
    const float inv = 1.f / sum;

    float oc[64];
    #pragma unroll
    for (int d = 0; d < 64; d++) oc[d] = 0.f;
    #pragma unroll
    for (int j = 0; j < 32; j++) {
        const float p = sc[j] * inv;
        #pragma unroll
        for (int d = 0; d < 64; d++) oc[d] += p * Vs[j * 64 + d];
    }
    const float g = gate[tok * HEADSN + h];
    #pragma unroll
    for (int d = 0; d < 64; d++) o[base + d] = rtf(oc[d] * g);
}

// ---------------- geglu: out = a * gelu_exact(g) (tf32-rounded) ----------------
__global__ void geglu_kernel(const float* __restrict__ hin, float* __restrict__ out)
{
    const int idx = blockIdx.x * blockDim.x + threadIdx.x;
    if (idx >= NTOK * DFFV) return;
    const int row = idx / DFFV, c = idx % DFFV;
    const float a = hin[(size_t)row * 2 * DFFV + c];
    const float g = hin[(size_t)row * 2 * DFFV + DFFV + c];
    const float ge = 0.5f * g * (1.f + erff(g * 0.70710678118654752f));
    out[idx] = rtf(a * ge);
}

// ---------------- host orchestration ----------------
extern "C" void kernel_launch(void* const* d_in, const int* in_sizes, int n_in,
                              void* d_out, int out_size)
{
    const float* tokens       = (const float*)d_in[0];
    const float* attn_norm_w  = (const float*)d_in[1];
    const float* Wq           = (const float*)d_in[2];
    const float* Wk           = (const float*)d_in[3];
    const float* Wv           = (const float*)d_in[4];
    const float* Wo           = (const float*)d_in[5];
    const float* Wg           = (const float*)d_in[6];
    const float* Wmix         = (const float*)d_in[7];
    const float* bmix         = (const float*)d_in[8];
    const float* kgam         = (const float*)d_in[9];
    const float* ff_norm_w    = (const float*)d_in[10];
    const float* Win          = (const float*)d_in[11];
    const float* b_in         = (const float*)d_in[12];
    const float* Wout         = (const float*)d_in[13];
    const float* b_out        = (const float*)d_in[14];
    const float* vr_norm_w    = (const float*)d_in[15];
    const float* vr_W         = (const float*)d_in[16];
    const float* final_norm_w = (const float*)d_in[17];

    float *x, *tn, *q, *k, *v, *rv, *o, *hbuf, *hg, *mix, *gate, *wt;
    cudaGetSymbolAddress((void**)&x,    g_x);
    cudaGetSymbolAddress((void**)&tn,   g_tn);
    cudaGetSymbolAddress((void**)&q,    g_q);
    cudaGetSymbolAddress((void**)&k,    g_k);
    cudaGetSymbolAddress((void**)&v,    g_v);
    cudaGetSymbolAddress((void**)&rv,   g_rv);
    cudaGetSymbolAddress((void**)&o,    g_o);
    cudaGetSymbolAddress((void**)&hbuf, g_h);
    cudaGetSymbolAddress((void**)&hg,   g_hg);
    cudaGetSymbolAddress((void**)&mix,  g_mix);
    cudaGetSymbolAddress((void**)&gate, g_gate);
    cudaGetSymbolAddress((void**)&wt,   g_wt);

    // per-layer transposed-weight slots
    float* wqT   = wt;
    float* wkT   = wt + 589824;
    float* wvT   = wt + 2 * 589824;
    float* woT   = wt + 3 * 589824;
    float* winT  = wt + 4 * 589824;             // [4096, 768]
    float* woutT = wt + 4 * 589824 + 3145728;   // [768, 2048]

    const int SPATIAL_SMEM = 3 * 256 * 64 * 4;   // 192 KB
    cudaFuncSetAttribute(attn_spatial_kernel,
                         cudaFuncAttributeMaxDynamicSharedMemorySize, SPATIAL_SMEM);
    cudaFuncSetAttribute(gemm_tc_kernel,
                         cudaFuncAttributeMaxDynamicSharedMemorySize, TCG_SMEM);

    const dim3 tb(32, 8);
    auto GEMM = [&](const float* A, const float* Bt, float* Cc,
                    const float* bias, const float* res, int M, int N, int K) {
        gemm_tc_kernel<<<dim3(N / 128, M / 128), 256, TCG_SMEM>>>(A, Bt, Cc, bias, res, M, N, K);
    };

    // value residual from original tokens (vr_W^T into wqT slot temporarily)
    transpose_kernel<<<dim3(24, 24), tb>>>(vr_W, wqT, 768, 768);
    rmsnorm_kernel<<<NTOK, 256>>>(tokens, vr_norm_w, tn, 1);
    GEMM(tn, wqT, rv, nullptr, nullptr, NTOK, DIMV, DIMV);
    copy_kernel<<<(NTOK * DIMV + 255) / 256, 256>>>(tokens, x, NTOK * DIMV);

    for (int i = 0; i < DEPTHN; i++) {
        const float* wq_i   = Wq   + (size_t)i * DIMV * DIMV;
        const float* wk_i   = Wk   + (size_t)i * DIMV * DIMV;
        const float* wv_i   = Wv   + (size_t)i * DIMV * DIMV;
        const float* wo_i   = Wo   + (size_t)i * DIMV * DIMV;
        const float* wg_i   = Wg   + (size_t)i * DIMV * HEADSN;
        const float* wmix_i = Wmix + (size_t)i * DIMV * HEADSN;
        const float* bmix_i = bmix + (size_t)i * HEADSN;
        const float* kgam_i = kgam + (size_t)i * HEADSN * DHV;
        const float* win_i  = Win  + (size_t)i * DIMV * 2 * DFFV;
        const float* bin_i  = b_in + (size_t)i * 2 * DFFV;
        const float* wout_i = Wout + (size_t)i * DFFV * DIMV;
        const float* bout_i = b_out + (size_t)i * DIMV;

        // transpose this layer's GEMM weights to [N, K]
        transpose_kernel<<<dim3(24, 24), tb>>>(wq_i, wqT, 768, 768);
        transpose_kernel<<<dim3(24, 24), tb>>>(wk_i, wkT, 768, 768);
        transpose_kernel<<<dim3(24, 24), tb>>>(wv_i, wvT, 768, 768);
        transpose_kernel<<<dim3(24, 24), tb>>>(wo_i, woT, 768, 768);
        transpose_kernel<<<dim3(128, 24), tb>>>(win_i, winT, 768, 4096);
        transpose_kernel<<<dim3(24, 64), tb>>>(wout_i, woutT, 2048, 768);

        // attention sublayer
        rmsnorm_kernel<<<NTOK, 256>>>(x, attn_norm_w + (size_t)i * DIMV, tn, 1);
        GEMM(tn, wqT, q, nullptr, nullptr, NTOK, DIMV, DIMV);
        GEMM(tn, wkT, k, nullptr, nullptr, NTOK, DIMV, DIMV);
        GEMM(tn, wvT, v, nullptr, nullptr, NTOK, DIMV, DIMV);
        mixgate_kernel<<<NTOK, 768>>>(tn, wmix_i, bmix_i, wg_i, mix, gate);
        vkfix_kernel<<<NTOK, 768>>>(v, rv, mix, k, kgam_i);

        if ((i + 1) % 4 == 0)
            attn_time_kernel<<<dim3(HEADSN, 512), 32>>>(q, k, v, gate, o);
        else
            attn_spatial_kernel<<<dim3(HEADSN, 64), 256, SPATIAL_SMEM>>>(q, k, v, gate, o);

        GEMM(o, woT, x, nullptr, x, NTOK, DIMV, DIMV);

        // feedforward sublayer
        rmsnorm_kernel<<<NTOK, 256>>>(x, ff_norm_w + (size_t)i * DIMV, tn, 1);
        GEMM(tn, winT, hbuf, bin_i, nullptr, NTOK, 2 * DFFV, DIMV);
        geglu_kernel<<<(NTOK * DFFV + 255) / 256, 256>>>(hbuf, hg);
        GEMM(hg, woutT, x, bout_i, x, NTOK, DIMV, DFFV);
    }

    rmsnorm_kernel<<<NTOK, 256>>>(x, final_norm_w, (float*)d_out, 0);
}